// round 2
// baseline (speedup 1.0000x reference)
#include <cuda_runtime.h>
#include <cstdint>

#define H 64
typedef unsigned long long ull;

// ---- packed f32x2 helpers (FFMA2/FADD2 are PTX-only on sm_103a) ----
__device__ __forceinline__ ull pack2(float a, float b){
    ull v; asm("mov.b64 %0, {%1, %2};" : "=l"(v) : "f"(a), "f"(b)); return v;
}
__device__ __forceinline__ void unpack2(ull v, float &a, float &b){
    asm("mov.b64 {%0, %1}, %2;" : "=f"(a), "=f"(b) : "l"(v));
}
__device__ __forceinline__ void fma2(ull &d, ull a, ull b){
    asm("fma.rn.f32x2 %0, %1, %2, %0;" : "+l"(d) : "l"(a), "l"(b));
}
__device__ __forceinline__ ull add2(ull a, ull b){
    ull d; asm("add.rn.f32x2 %0, %1, %2;" : "=l"(d) : "l"(a), "l"(b)); return d;
}

__device__ __forceinline__ float elu(float x){
    return x > 0.f ? x : (__expf(x) - 1.f);
}

// Interleaved weight pairs: qw[k*64+j] = (W2[k,j], M[k,j]), M[k,j] = W2[k,j]*C[j,k],
// C = W1 @ W3. Accumulating fma2 with (h1_j, min(h1_j,0)) yields (a2_k, trace_k) at once.
__global__ __launch_bounds__(128, 4)
void odefunc_kernel(const float* __restrict__ zlp,
                    const float* __restrict__ W1, const float* __restrict__ b1,
                    const float* __restrict__ W2, const float* __restrict__ b2,
                    const float* __restrict__ W3, const float* __restrict__ b3,
                    float* __restrict__ out, int B)
{
    __shared__ __align__(16) ull    sQW[H*H];      // 32 KB interleaved (W2, M) pairs
    __shared__ __align__(8)  float2 sBR[H];        // (b2[k], rowsum_M[k])
    __shared__ __align__(8)  float2 sW3[H];        // (W3[0,k], W3[1,k])
    __shared__ float sW1a[H], sW1b[H], sB1[H];
    __shared__ float sB3[2];

    const int tid = threadIdx.x;

    for (int j = tid; j < H; j += blockDim.x){
        sW1a[j] = W1[2*j]; sW1b[j] = W1[2*j+1]; sB1[j] = b1[j];
        sW3[j] = make_float2(W3[j], W3[H + j]);
    }
    if (tid < 2) sB3[tid] = b3[tid];

    for (int idx = tid; idx < H*H; idx += blockDim.x){
        int k = idx >> 6, j = idx & 63;
        float w2 = W2[idx];
        float c  = fmaf(W1[2*j], W3[k], W1[2*j+1] * W3[H + k]);   // C[j][k]
        sQW[idx] = pack2(w2, w2 * c);
    }
    __syncthreads();

    if (tid < H){                                  // row-sums of M + pack with b2
        float s = 0.f;
        #pragma unroll 8
        for (int j = 0; j < H; j++){
            float lo, hi; unpack2(sQW[tid*H + j], lo, hi);
            s += hi;
        }
        sBR[tid] = make_float2(b2[tid], s);
    }
    __syncthreads();

    const float b30 = sB3[0], b31 = sB3[1];
    const int   half   = tid & 1;                  // lane pair: each lane owns 32 j's
    const int   stride = (gridDim.x * blockDim.x) >> 1;

    for (int p = (blockIdx.x * blockDim.x + tid) >> 1; p < B; p += stride){
        const float z0 = zlp[3*p], z1 = zlp[3*p + 1];

        // Layer 1 for this lane's 32 j's: ph[jj] = (h1_j, min(h1_j,0))
        ull ph[H/2];
        const int jbase = half << 5;
        #pragma unroll
        for (int jj = 0; jj < H/2; jj++){
            int j = jbase + jj;
            float a = fmaf(sW1a[j], z0, fmaf(sW1b[j], z1, sB1[j]));
            float h = elu(a);
            ph[jj] = pack2(h, fminf(h, 0.f));
        }

        float o0 = 0.f, o1 = 0.f, tr = 0.f;
        #pragma unroll 1
        for (int k = 0; k < H; k++){
            const ulonglong2* row =
                reinterpret_cast<const ulonglong2*>(&sQW[(k << 6) + jbase]);
            ull a0 = 0ull, a1 = 0ull, a2 = 0ull, a3 = 0ull;
            #pragma unroll 4
            for (int q = 0; q < 16; q += 2){
                ulonglong2 w0 = row[q];
                fma2(a0, w0.x, ph[2*q]);
                fma2(a1, w0.y, ph[2*q + 1]);
                ulonglong2 w1 = row[q + 1];
                fma2(a2, w1.x, ph[2*q + 2]);
                fma2(a3, w1.y, ph[2*q + 3]);
            }
            ull s = add2(add2(a0, a1), add2(a2, a3));
            // combine lane-pair partials: both lanes get the full (a2_k, t_k)
            s = add2(s, __shfl_xor_sync(0xffffffffu, s, 1));

            float va, vt; unpack2(s, va, vt);
            float2 br = sBR[k];
            float h2 = elu(va + br.x);
            float2 w3 = sW3[k];
            o0 = fmaf(w3.x, h2, o0);
            o1 = fmaf(w3.y, h2, o1);
            float g2 = 1.f + fminf(h2, 0.f);
            tr = fmaf(g2, vt + br.y, tr);
        }

        if (half == 0){
            out[3*p]     = o0 + b30;
            out[3*p + 1] = o1 + b31;
            out[3*p + 2] = -tr;
        }
    }
}

extern "C" void kernel_launch(void* const* d_in, const int* in_sizes, int n_in,
                              void* d_out, int out_size)
{
    // metadata order: t, z_and_logp, W1, b1, W2, b2, W3, b3
    const float* zlp = (const float*)d_in[1];
    const float* W1  = (const float*)d_in[2];
    const float* b1  = (const float*)d_in[3];
    const float* W2  = (const float*)d_in[4];
    const float* b2  = (const float*)d_in[5];
    const float* W3  = (const float*)d_in[6];
    const float* b3  = (const float*)d_in[7];
    float* out = (float*)d_out;
    int B = in_sizes[1] / 3;

    const int block = 128;
    const int grid  = 592;   // 148 SMs x 4 resident blocks; grid-stride over sample pairs
    odefunc_kernel<<<grid, block>>>(zlp, W1, b1, W2, b2, W3, b3, out, B);
}

// round 4
// speedup vs baseline: 7.7315x; 7.7315x over previous
#include <cuda_runtime.h>
#include <cuda_bf16.h>
#include <cstdint>

#define H 64
#define TILE 256
#define NT 256
#define RS 144                  // smem row stride (bytes): 9*16 -> conflict-free ldmatrix

// ---- smem layout (bytes) ----
#define OFF_AH   0               // h hi      : 256 x 144
#define OFF_AL   36864           // h lo
#define OFF_NH   73728           // min hi
#define OFF_NL   110592          // min lo
#define OFF_W2H  147456          // W2 hi     : 64 x 144
#define OFF_W2L  156672
#define OFF_MH   165888          // M hi
#define OFF_ML   175104
#define OFF_TBL  184320          // float4[64]: (b2, rsM, W3_0, W3_1)
#define OFF_W1A  185344          // float[64]
#define OFF_W1B  185600
#define OFF_B1   185856
#define OFF_B3   186112          // float[2]
#define SMEM_TOTAL 186368

__device__ __forceinline__ uint32_t smem_u32(const void* p){
    uint32_t a;
    asm("{ .reg .u64 t; cvta.to.shared.u64 t, %1; cvt.u32.u64 %0, t; }" : "=r"(a) : "l"(p));
    return a;
}
__device__ __forceinline__ void ldm_x4(uint32_t* r, uint32_t addr){
    asm volatile("ldmatrix.sync.aligned.m8n8.x4.shared.b16 {%0,%1,%2,%3}, [%4];"
        : "=r"(r[0]),"=r"(r[1]),"=r"(r[2]),"=r"(r[3]) : "r"(addr));
}
__device__ __forceinline__ void ldm_x2(uint32_t* r, uint32_t addr){
    asm volatile("ldmatrix.sync.aligned.m8n8.x2.shared.b16 {%0,%1}, [%2];"
        : "=r"(r[0]),"=r"(r[1]) : "r"(addr));
}
__device__ __forceinline__ void mma_bf16(float* d, const uint32_t* a, const uint32_t* b){
    asm volatile("mma.sync.aligned.m16n8k16.row.col.f32.bf16.bf16.f32 "
        "{%0,%1,%2,%3}, {%4,%5,%6,%7}, {%8,%9}, {%0,%1,%2,%3};"
        : "+f"(d[0]),"+f"(d[1]),"+f"(d[2]),"+f"(d[3])
        : "r"(a[0]),"r"(a[1]),"r"(a[2]),"r"(a[3]), "r"(b[0]),"r"(b[1]));
}
__device__ __forceinline__ float elu(float x){ return x > 0.f ? x : (__expf(x) - 1.f); }

// pack two floats to bf16x2 (lo half = first) and return hi/lo split
__device__ __forceinline__ void split2(float a, float b, uint32_t &hi, uint32_t &lo){
    __nv_bfloat162 v = __floats2bfloat162_rn(a, b);
    hi = *reinterpret_cast<uint32_t*>(&v);
    float fa = __uint_as_float(hi << 16);            // exact float of bf16(a)
    float fb = __uint_as_float(hi & 0xffff0000u);    // exact float of bf16(b)
    __nv_bfloat162 w = __floats2bfloat162_rn(a - fa, b - fb);
    lo = *reinterpret_cast<uint32_t*>(&w);
}

__global__ __launch_bounds__(NT, 1)
void odefunc_mma(const float* __restrict__ zlp,
                 const float* __restrict__ W1, const float* __restrict__ b1,
                 const float* __restrict__ W2, const float* __restrict__ b2,
                 const float* __restrict__ W3, const float* __restrict__ b3,
                 float* __restrict__ out, int B, int ntiles)
{
    extern __shared__ char sm[];
    const uint32_t smb = smem_u32(sm);
    const int tid = threadIdx.x, w = tid >> 5, lane = tid & 31;

    float*  sW1a = (float*)(sm + OFF_W1A);
    float*  sW1b = (float*)(sm + OFF_W1B);
    float*  sB1  = (float*)(sm + OFF_B1);
    float*  sB3  = (float*)(sm + OFF_B3);
    float4* sTBL = (float4*)(sm + OFF_TBL);

    // ---------- per-CTA weight prep ----------
    for (int j = tid; j < H; j += NT){
        sW1a[j] = W1[2*j]; sW1b[j] = W1[2*j+1]; sB1[j] = b1[j];
    }
    if (tid < 2) sB3[tid] = b3[tid];

    for (int idx = tid; idx < H*H; idx += NT){
        int n = idx >> 6, j = idx & 63;            // n = output neuron, j = input
        float w2 = W2[idx];
        float c  = fmaf(W1[2*j], W3[n], W1[2*j+1] * W3[H + n]);   // C[j][n]
        float m  = w2 * c;
        uint32_t off = (uint32_t)(n*RS + 2*j);
        __nv_bfloat16 h = __float2bfloat16_rn(w2);
        *(__nv_bfloat16*)(sm + OFF_W2H + off) = h;
        *(__nv_bfloat16*)(sm + OFF_W2L + off) = __float2bfloat16_rn(w2 - __bfloat162float(h));
        __nv_bfloat16 hm = __float2bfloat16_rn(m);
        *(__nv_bfloat16*)(sm + OFF_MH + off) = hm;
        *(__nv_bfloat16*)(sm + OFF_ML + off) = __float2bfloat16_rn(m - __bfloat162float(hm));
    }
    if (tid < H){
        float s = 0.f;
        #pragma unroll 8
        for (int j = 0; j < H; j++){
            float c = fmaf(W1[2*j], W3[tid], W1[2*j+1] * W3[H + tid]);
            s += W2[tid*H + j] * c;
        }
        sTBL[tid] = make_float4(b2[tid], s, W3[tid], W3[H + tid]);
    }
    __syncthreads();

    const float b30 = sB3[0], b31 = sB3[1];

    // ldmatrix lane address components
    const int aRow  = (lane & 7) + ((lane >> 3) & 1) * 8;  // A: row within 16
    const int aColB = (lane >> 4) * 16;                    // A: byte col offset (0 or 16)
    const int bRow  = lane & 7;                            // B: n within 8 (lanes 0-15 used)
    const int bColB = ((lane >> 3) & 1) * 16;

    for (int tile = blockIdx.x; tile < ntiles; tile += gridDim.x){
        const int base = tile * TILE;
        const int s = base + tid;
        const bool ok = (s < B);
        float z0 = 0.f, z1 = 0.f;
        if (ok){ z0 = zlp[3*s]; z1 = zlp[3*s + 1]; }

        // ---- fill this thread's A row (h hi/lo, min hi/lo), 16B chunks ----
        {
            const uint32_t rbase = (uint32_t)tid * RS;
            #pragma unroll
            for (int jb = 0; jb < 8; jb++){
                uint4 vh, vl, uh, ul;
                uint32_t* ph = (uint32_t*)&vh; uint32_t* pl = (uint32_t*)&vl;
                uint32_t* qh = (uint32_t*)&uh; uint32_t* ql = (uint32_t*)&ul;
                #pragma unroll
                for (int q = 0; q < 4; q++){
                    int j = jb*8 + 2*q;
                    float a0 = fmaf(sW1a[j],   z0, fmaf(sW1b[j],   z1, sB1[j]));
                    float a1 = fmaf(sW1a[j+1], z0, fmaf(sW1b[j+1], z1, sB1[j+1]));
                    float h0 = ok ? elu(a0) : 0.f;
                    float h1 = ok ? elu(a1) : 0.f;
                    float m0 = fminf(h0, 0.f), m1 = fminf(h1, 0.f);
                    split2(h0, h1, ph[q], pl[q]);
                    split2(m0, m1, qh[q], ql[q]);
                }
                uint32_t o = rbase + jb*16;
                *(uint4*)(sm + OFF_AH + o) = vh;
                *(uint4*)(sm + OFF_AL + o) = vl;
                *(uint4*)(sm + OFF_NH + o) = uh;
                *(uint4*)(sm + OFF_NL + o) = ul;
            }
        }
        __syncwarp();

        // ---- warp-local GEMM: 32 samples (2 m-tiles), N=64 in 2 halves ----
        float o0[2][2] = {{0,0},{0,0}}, o1[2][2] = {{0,0},{0,0}}, trr[2][2] = {{0,0},{0,0}};
        const uint32_t aBase = smb + (uint32_t)((w*32 + aRow) * RS + aColB);

        #pragma unroll
        for (int half = 0; half < 2; half++){
            float dv[2][4][4], dt[2][4][4];
            #pragma unroll
            for (int mt = 0; mt < 2; mt++)
                #pragma unroll
                for (int ng = 0; ng < 4; ng++)
                    #pragma unroll
                    for (int e = 0; e < 4; e++){ dv[mt][ng][e] = 0.f; dt[mt][ng][e] = 0.f; }

            #pragma unroll
            for (int kc = 0; kc < 4; kc++){
                // B fragments: 4 n-groups x {W2h, W2l, Mh, Ml}
                uint32_t bf[4][4][2];
                #pragma unroll
                for (int ng = 0; ng < 4; ng++){
                    int n = half*32 + ng*8 + bRow;
                    uint32_t boff = (uint32_t)(n*RS + kc*32 + bColB);
                    ldm_x2(bf[ng][0], smb + OFF_W2H + boff);
                    ldm_x2(bf[ng][1], smb + OFF_W2L + boff);
                    ldm_x2(bf[ng][2], smb + OFF_MH  + boff);
                    ldm_x2(bf[ng][3], smb + OFF_ML  + boff);
                }
                #pragma unroll
                for (int mt = 0; mt < 2; mt++){
                    uint32_t ah[4], al[4], nh[4], nl[4];
                    uint32_t ao = aBase + (uint32_t)(mt*16*RS + kc*32);
                    ldm_x4(ah, ao + OFF_AH);
                    ldm_x4(al, ao + OFF_AL);
                    ldm_x4(nh, ao + OFF_NH);
                    ldm_x4(nl, ao + OFF_NL);
                    #pragma unroll
                    for (int ng = 0; ng < 4; ng++){
                        mma_bf16(dv[mt][ng], ah, bf[ng][0]);
                        mma_bf16(dv[mt][ng], al, bf[ng][0]);
                        mma_bf16(dv[mt][ng], ah, bf[ng][1]);
                        mma_bf16(dt[mt][ng], nh, bf[ng][2]);
                        mma_bf16(dt[mt][ng], nl, bf[ng][2]);
                        mma_bf16(dt[mt][ng], nh, bf[ng][3]);
                    }
                }
            }

            // ---- epilogue for this half ----
            #pragma unroll
            for (int mt = 0; mt < 2; mt++)
                #pragma unroll
                for (int ng = 0; ng < 4; ng++){
                    int n0 = half*32 + ng*8 + 2*(lane & 3);
                    float4 t0 = sTBL[n0], t1 = sTBL[n0 + 1];
                    #pragma unroll
                    for (int rr = 0; rr < 2; rr++){
                        float v0 = dv[mt][ng][2*rr],     tv0 = dt[mt][ng][2*rr];
                        float v1 = dv[mt][ng][2*rr + 1], tv1 = dt[mt][ng][2*rr + 1];
                        float h2 = elu(v0 + t0.x);
                        o0[mt][rr]  = fmaf(t0.z, h2, o0[mt][rr]);
                        o1[mt][rr]  = fmaf(t0.w, h2, o1[mt][rr]);
                        trr[mt][rr] = fmaf(1.f + fminf(h2, 0.f), tv0 + t0.y, trr[mt][rr]);
                        float h3 = elu(v1 + t1.x);
                        o0[mt][rr]  = fmaf(t1.z, h3, o0[mt][rr]);
                        o1[mt][rr]  = fmaf(t1.w, h3, o1[mt][rr]);
                        trr[mt][rr] = fmaf(1.f + fminf(h3, 0.f), tv1 + t1.y, trr[mt][rr]);
                    }
                }
        }

        // ---- reduce across the 4 lanes of each row group, store ----
        #pragma unroll
        for (int mt = 0; mt < 2; mt++)
            #pragma unroll
            for (int rr = 0; rr < 2; rr++){
                o0[mt][rr]  += __shfl_xor_sync(0xffffffffu, o0[mt][rr], 1);
                o0[mt][rr]  += __shfl_xor_sync(0xffffffffu, o0[mt][rr], 2);
                o1[mt][rr]  += __shfl_xor_sync(0xffffffffu, o1[mt][rr], 1);
                o1[mt][rr]  += __shfl_xor_sync(0xffffffffu, o1[mt][rr], 2);
                trr[mt][rr] += __shfl_xor_sync(0xffffffffu, trr[mt][rr], 1);
                trr[mt][rr] += __shfl_xor_sync(0xffffffffu, trr[mt][rr], 2);
            }
        if ((lane & 3) == 0){
            int g = lane >> 2;
            #pragma unroll
            for (int mt = 0; mt < 2; mt++)
                #pragma unroll
                for (int rr = 0; rr < 2; rr++){
                    int s2 = base + w*32 + mt*16 + g + rr*8;
                    if (s2 < B){
                        out[3*s2]     = o0[mt][rr] + b30;
                        out[3*s2 + 1] = o1[mt][rr] + b31;
                        out[3*s2 + 2] = -trr[mt][rr];
                    }
                }
        }
        __syncwarp();
    }
}

extern "C" void kernel_launch(void* const* d_in, const int* in_sizes, int n_in,
                              void* d_out, int out_size)
{
    // metadata order: t, z_and_logp, W1, b1, W2, b2, W3, b3
    const float* zlp = (const float*)d_in[1];
    const float* W1  = (const float*)d_in[2];
    const float* b1  = (const float*)d_in[3];
    const float* W2  = (const float*)d_in[4];
    const float* b2  = (const float*)d_in[5];
    const float* W3  = (const float*)d_in[6];
    const float* b3  = (const float*)d_in[7];
    float* out = (float*)d_out;
    int B = in_sizes[1] / 3;
    int ntiles = (B + TILE - 1) / TILE;

    cudaFuncSetAttribute(odefunc_mma, cudaFuncAttributeMaxDynamicSharedMemorySize, SMEM_TOTAL);
    int grid = 148;
    if (grid > ntiles) grid = ntiles;
    odefunc_mma<<<grid, NT, SMEM_TOTAL>>>(zlp, W1, b1, W2, b2, W3, b3, out, B, ntiles);
}

// round 5
// speedup vs baseline: 10.5853x; 1.3691x over previous
#include <cuda_runtime.h>
#include <cuda_fp16.h>
#include <cstdint>

#define H 64
#define TILE 256
#define NT 256
#define RS 144                  // smem row stride (bytes): 9*16 -> conflict-free ldmatrix

// ---- smem layout (bytes) ----
#define OFF_AH   0               // h (fp16)        : 256 x 144
#define OFF_NH   36864           // min(h,0) (fp16) : 256 x 144
#define OFF_W2H  73728           // W2 hi           : 64 x 144
#define OFF_W2L  82944           // W2 lo
#define OFF_MH   92160           // M hi
#define OFF_ML   101376          // M lo
#define OFF_TBL  110592          // float4[64]: (b2, rsM, W3_0, W3_1)
#define OFF_W1A  111616          // float[64]
#define OFF_W1B  111872
#define OFF_B1   112128
#define OFF_B3   112384          // float[2]
#define SMEM_TOTAL 112640

__device__ __forceinline__ uint32_t smem_u32(const void* p){
    uint32_t a;
    asm("{ .reg .u64 t; cvta.to.shared.u64 t, %1; cvt.u32.u64 %0, t; }" : "=r"(a) : "l"(p));
    return a;
}
__device__ __forceinline__ void ldm_x4(uint32_t* r, uint32_t addr){
    asm volatile("ldmatrix.sync.aligned.m8n8.x4.shared.b16 {%0,%1,%2,%3}, [%4];"
        : "=r"(r[0]),"=r"(r[1]),"=r"(r[2]),"=r"(r[3]) : "r"(addr));
}
__device__ __forceinline__ void mma_f16(float* d, const uint32_t* a, const uint32_t* b){
    asm volatile("mma.sync.aligned.m16n8k16.row.col.f32.f16.f16.f32 "
        "{%0,%1,%2,%3}, {%4,%5,%6,%7}, {%8,%9}, {%0,%1,%2,%3};"
        : "+f"(d[0]),"+f"(d[1]),"+f"(d[2]),"+f"(d[3])
        : "r"(a[0]),"r"(a[1]),"r"(a[2]),"r"(a[3]), "r"(b[0]),"r"(b[1]));
}
__device__ __forceinline__ float elu(float x){ return x > 0.f ? x : (__expf(x) - 1.f); }

__device__ __forceinline__ uint32_t packh2(float a, float b){
    __half2 v = __floats2half2_rn(a, b);
    return *reinterpret_cast<uint32_t*>(&v);
}

__global__ __launch_bounds__(NT, 1)
void odefunc_mma(const float* __restrict__ zlp,
                 const float* __restrict__ W1, const float* __restrict__ b1,
                 const float* __restrict__ W2, const float* __restrict__ b2,
                 const float* __restrict__ W3, const float* __restrict__ b3,
                 float* __restrict__ out, int B, int ntiles)
{
    extern __shared__ char sm[];
    const uint32_t smb = smem_u32(sm);
    const int tid = threadIdx.x, w = tid >> 5, lane = tid & 31;

    float*  sW1a = (float*)(sm + OFF_W1A);
    float*  sW1b = (float*)(sm + OFF_W1B);
    float*  sB1  = (float*)(sm + OFF_B1);
    float*  sB3  = (float*)(sm + OFF_B3);
    float4* sTBL = (float4*)(sm + OFF_TBL);

    // ---------- per-CTA weight prep ----------
    for (int j = tid; j < H; j += NT){
        sW1a[j] = W1[2*j]; sW1b[j] = W1[2*j+1]; sB1[j] = b1[j];
    }
    if (tid < 2) sB3[tid] = b3[tid];

    for (int idx = tid; idx < H*H; idx += NT){
        int n = idx >> 6, j = idx & 63;            // n = output neuron, j = input
        float w2 = W2[idx];
        float c  = fmaf(W1[2*j], W3[n], W1[2*j+1] * W3[H + n]);   // C[j][n]
        float m  = w2 * c;                                        // trace matrix
        uint32_t off = (uint32_t)(n*RS + 2*j);
        __half hv = __float2half_rn(w2);
        *(__half*)(sm + OFF_W2H + off) = hv;
        *(__half*)(sm + OFF_W2L + off) = __float2half_rn(w2 - __half2float(hv));
        __half hm = __float2half_rn(m);
        *(__half*)(sm + OFF_MH + off) = hm;
        *(__half*)(sm + OFF_ML + off) = __float2half_rn(m - __half2float(hm));
    }
    if (tid < H){
        float s = 0.f;
        #pragma unroll 8
        for (int j = 0; j < H; j++){
            float c = fmaf(W1[2*j], W3[tid], W1[2*j+1] * W3[H + tid]);
            s += W2[tid*H + j] * c;
        }
        sTBL[tid] = make_float4(b2[tid], s, W3[tid], W3[H + tid]);
    }
    __syncthreads();

    const float b30 = sB3[0], b31 = sB3[1];

    // ldmatrix lane address components
    const int aRow  = (lane & 7) + ((lane >> 3) & 1) * 8;     // A x4: rows within 16
    const int aColB = (lane >> 4) * 16;
    const int bRow4 = (lane & 7) + ((lane >> 4) & 1) * 8;     // B x4: n within ng-pair
    const int bCol4 = ((lane >> 3) & 1) * 16;

    const uint32_t aAH = smb + OFF_AH + (uint32_t)((w*32 + aRow)*RS + aColB);
    const uint32_t aNH = smb + OFF_NH + (uint32_t)((w*32 + aRow)*RS + aColB);
    const uint32_t bBase = (uint32_t)(bRow4*RS + bCol4);

    for (int tile = blockIdx.x; tile < ntiles; tile += gridDim.x){
        const int base = tile * TILE;
        const int s = base + tid;
        const bool ok = (s < B);
        float z0 = 0.f, z1 = 0.f;
        if (ok){ z0 = zlp[3*s]; z1 = zlp[3*s + 1]; }

        // ---- fill this thread's A rows: h and min(h,0) as fp16, 16B chunks ----
        {
            const uint32_t rbase = (uint32_t)tid * RS;
            #pragma unroll
            for (int jb = 0; jb < 8; jb++){
                uint4 vh, un;
                uint32_t* ph = (uint32_t*)&vh;
                uint32_t* pn = (uint32_t*)&un;
                #pragma unroll
                for (int q = 0; q < 4; q++){
                    int j = jb*8 + 2*q;
                    float a0 = fmaf(sW1a[j],   z0, fmaf(sW1b[j],   z1, sB1[j]));
                    float a1 = fmaf(sW1a[j+1], z0, fmaf(sW1b[j+1], z1, sB1[j+1]));
                    float h0 = ok ? elu(a0) : 0.f;
                    float h1 = ok ? elu(a1) : 0.f;
                    ph[q] = packh2(h0, h1);
                    pn[q] = packh2(fminf(h0, 0.f), fminf(h1, 0.f));
                }
                uint32_t o = rbase + jb*16;
                *(uint4*)(sm + OFF_AH + o) = vh;
                *(uint4*)(sm + OFF_NH + o) = un;
            }
        }
        __syncwarp();

        // ---- warp-local GEMM: 32 samples (2 m-tiles), N=64 in 2 halves ----
        float o0[2][2] = {{0,0},{0,0}}, o1[2][2] = {{0,0},{0,0}}, trr[2][2] = {{0,0},{0,0}};

        #pragma unroll
        for (int half = 0; half < 2; half++){
            float dv[2][4][4], dt[2][4][4];
            #pragma unroll
            for (int mt = 0; mt < 2; mt++)
                #pragma unroll
                for (int ng = 0; ng < 4; ng++)
                    #pragma unroll
                    for (int e = 0; e < 4; e++){ dv[mt][ng][e] = 0.f; dt[mt][ng][e] = 0.f; }

            #pragma unroll
            for (int kc = 0; kc < 4; kc++){
                // B fragments: x4 loads cover an ng-pair; 4 mats each
                uint32_t bv0[4][2], bv1[4][2], bt0[4][2], bt1[4][2];
                #pragma unroll
                for (int ngp = 0; ngp < 2; ngp++){
                    uint32_t roff = bBase + (uint32_t)((half*32 + ngp*16)*RS + kc*32);
                    uint32_t r[4];
                    ldm_x4(r, smb + OFF_W2H + roff);
                    bv0[2*ngp][0]=r[0]; bv0[2*ngp][1]=r[1]; bv0[2*ngp+1][0]=r[2]; bv0[2*ngp+1][1]=r[3];
                    ldm_x4(r, smb + OFF_W2L + roff);
                    bv1[2*ngp][0]=r[0]; bv1[2*ngp][1]=r[1]; bv1[2*ngp+1][0]=r[2]; bv1[2*ngp+1][1]=r[3];
                    ldm_x4(r, smb + OFF_MH + roff);
                    bt0[2*ngp][0]=r[0]; bt0[2*ngp][1]=r[1]; bt0[2*ngp+1][0]=r[2]; bt0[2*ngp+1][1]=r[3];
                    ldm_x4(r, smb + OFF_ML + roff);
                    bt1[2*ngp][0]=r[0]; bt1[2*ngp][1]=r[1]; bt1[2*ngp+1][0]=r[2]; bt1[2*ngp+1][1]=r[3];
                }
                #pragma unroll
                for (int mt = 0; mt < 2; mt++){
                    uint32_t ah[4], nh[4];
                    uint32_t ao = (uint32_t)(mt*16*RS + kc*32);
                    ldm_x4(ah, aAH + ao);
                    ldm_x4(nh, aNH + ao);
                    #pragma unroll
                    for (int ng = 0; ng < 4; ng++){
                        mma_f16(dv[mt][ng], ah, bv0[ng]);   // Ah * W2h
                        mma_f16(dv[mt][ng], ah, bv1[ng]);   // Ah * W2l
                        mma_f16(dt[mt][ng], nh, bt0[ng]);   // Nh * Mh
                        mma_f16(dt[mt][ng], nh, bt1[ng]);   // Nh * Ml
                    }
                }
            }

            // ---- epilogue for this half ----
            #pragma unroll
            for (int ng = 0; ng < 4; ng++){
                int n0 = half*32 + ng*8 + 2*(lane & 3);
                float4 t0 = sTBL[n0], t1 = sTBL[n0 + 1];
                #pragma unroll
                for (int mt = 0; mt < 2; mt++){
                    #pragma unroll
                    for (int rr = 0; rr < 2; rr++){
                        float v0 = dv[mt][ng][2*rr],     tv0 = dt[mt][ng][2*rr];
                        float v1 = dv[mt][ng][2*rr + 1], tv1 = dt[mt][ng][2*rr + 1];
                        float h2 = elu(v0 + t0.x);
                        o0[mt][rr]  = fmaf(t0.z, h2, o0[mt][rr]);
                        o1[mt][rr]  = fmaf(t0.w, h2, o1[mt][rr]);
                        trr[mt][rr] = fmaf(1.f + fminf(h2, 0.f), tv0 + t0.y, trr[mt][rr]);
                        float h3 = elu(v1 + t1.x);
                        o0[mt][rr]  = fmaf(t1.z, h3, o0[mt][rr]);
                        o1[mt][rr]  = fmaf(t1.w, h3, o1[mt][rr]);
                        trr[mt][rr] = fmaf(1.f + fminf(h3, 0.f), tv1 + t1.y, trr[mt][rr]);
                    }
                }
            }
        }

        // ---- reduce across the 4 lanes of each row group, store ----
        #pragma unroll
        for (int mt = 0; mt < 2; mt++)
            #pragma unroll
            for (int rr = 0; rr < 2; rr++){
                o0[mt][rr]  += __shfl_xor_sync(0xffffffffu, o0[mt][rr], 1);
                o0[mt][rr]  += __shfl_xor_sync(0xffffffffu, o0[mt][rr], 2);
                o1[mt][rr]  += __shfl_xor_sync(0xffffffffu, o1[mt][rr], 1);
                o1[mt][rr]  += __shfl_xor_sync(0xffffffffu, o1[mt][rr], 2);
                trr[mt][rr] += __shfl_xor_sync(0xffffffffu, trr[mt][rr], 1);
                trr[mt][rr] += __shfl_xor_sync(0xffffffffu, trr[mt][rr], 2);
            }
        if ((lane & 3) == 0){
            int g = lane >> 2;
            #pragma unroll
            for (int mt = 0; mt < 2; mt++)
                #pragma unroll
                for (int rr = 0; rr < 2; rr++){
                    int s2 = base + w*32 + mt*16 + g + rr*8;
                    if (s2 < B){
                        out[3*s2]     = o0[mt][rr] + b30;
                        out[3*s2 + 1] = o1[mt][rr] + b31;
                        out[3*s2 + 2] = -trr[mt][rr];
                    }
                }
        }
        __syncwarp();
    }
}

extern "C" void kernel_launch(void* const* d_in, const int* in_sizes, int n_in,
                              void* d_out, int out_size)
{
    // metadata order: t, z_and_logp, W1, b1, W2, b2, W3, b3
    const float* zlp = (const float*)d_in[1];
    const float* W1  = (const float*)d_in[2];
    const float* b1  = (const float*)d_in[3];
    const float* W2  = (const float*)d_in[4];
    const float* b2  = (const float*)d_in[5];
    const float* W3  = (const float*)d_in[6];
    const float* b3  = (const float*)d_in[7];
    float* out = (float*)d_out;
    int B = in_sizes[1] / 3;
    int ntiles = (B + TILE - 1) / TILE;

    cudaFuncSetAttribute(odefunc_mma, cudaFuncAttributeMaxDynamicSharedMemorySize, SMEM_TOTAL);
    int grid = 148;
    if (grid > ntiles) grid = ntiles;
    odefunc_mma<<<grid, NT, SMEM_TOTAL>>>(zlp, W1, b1, W2, b2, W3, b3, out, B, ntiles);
}

// round 6
// speedup vs baseline: 12.2028x; 1.1528x over previous
#include <cuda_runtime.h>
#include <cuda_fp16.h>
#include <cstdint>

#define H 64
#define TILE 256
#define NT 256
#define RS 144                  // smem row stride (bytes): 9*16 -> conflict-free ldmatrix

// ---- smem layout (bytes) ----
#define OFF_AH   0               // h (fp16)        : 256 x 144
#define OFF_NH   36864           // min(h,0) (fp16) : 256 x 144
#define OFF_W2H  73728           // W2 (fp16)       : 64 x 144
#define OFF_MH   82944           // M  (fp16)       : 64 x 144
#define OFF_TBL  92160           // float4[64]: (b2, rsM, W3_0, W3_1)
#define OFF_W1A  93184           // float[64]
#define OFF_W1B  93440
#define OFF_B1   93696
#define OFF_B3   93952           // float[2]
#define SMEM_TOTAL 94208

__device__ __forceinline__ uint32_t smem_u32(const void* p){
    uint32_t a;
    asm("{ .reg .u64 t; cvta.to.shared.u64 t, %1; cvt.u32.u64 %0, t; }" : "=r"(a) : "l"(p));
    return a;
}
__device__ __forceinline__ void ldm_x4(uint32_t* r, uint32_t addr){
    asm volatile("ldmatrix.sync.aligned.m8n8.x4.shared.b16 {%0,%1,%2,%3}, [%4];"
        : "=r"(r[0]),"=r"(r[1]),"=r"(r[2]),"=r"(r[3]) : "r"(addr));
}
__device__ __forceinline__ void mma_f16(float* d, const uint32_t* a, const uint32_t* b){
    asm volatile("mma.sync.aligned.m16n8k16.row.col.f32.f16.f16.f32 "
        "{%0,%1,%2,%3}, {%4,%5,%6,%7}, {%8,%9}, {%0,%1,%2,%3};"
        : "+f"(d[0]),"+f"(d[1]),"+f"(d[2]),"+f"(d[3])
        : "r"(a[0]),"r"(a[1]),"r"(a[2]),"r"(a[3]), "r"(b[0]),"r"(b[1]));
}
__device__ __forceinline__ float elu(float x){ return x > 0.f ? x : (__expf(x) - 1.f); }

__device__ __forceinline__ uint32_t packh2(float a, float b){
    __half2 v = __floats2half2_rn(a, b);
    return *reinterpret_cast<uint32_t*>(&v);
}

__global__ __launch_bounds__(NT, 1)
void odefunc_mma(const float* __restrict__ zlp,
                 const float* __restrict__ W1, const float* __restrict__ b1,
                 const float* __restrict__ W2, const float* __restrict__ b2,
                 const float* __restrict__ W3, const float* __restrict__ b3,
                 float* __restrict__ out, int B, int ntiles)
{
    extern __shared__ char sm[];
    const uint32_t smb = smem_u32(sm);
    const int tid = threadIdx.x, w = tid >> 5, lane = tid & 31;

    float*  sW1a = (float*)(sm + OFF_W1A);
    float*  sW1b = (float*)(sm + OFF_W1B);
    float*  sB1  = (float*)(sm + OFF_B1);
    float*  sB3  = (float*)(sm + OFF_B3);
    float4* sTBL = (float4*)(sm + OFF_TBL);

    // ---------- per-CTA weight prep ----------
    for (int j = tid; j < H; j += NT){
        sW1a[j] = W1[2*j]; sW1b[j] = W1[2*j+1]; sB1[j] = b1[j];
    }
    if (tid < 2) sB3[tid] = b3[tid];

    for (int idx = tid; idx < H*H; idx += NT){
        int n = idx >> 6, j = idx & 63;            // n = output neuron, j = input
        float w2 = W2[idx];
        float c  = fmaf(W1[2*j], W3[n], W1[2*j+1] * W3[H + n]);   // C[j][n]
        uint32_t off = (uint32_t)(n*RS + 2*j);
        *(__half*)(sm + OFF_W2H + off) = __float2half_rn(w2);
        *(__half*)(sm + OFF_MH  + off) = __float2half_rn(w2 * c);
    }
    if (tid < H){
        float s = 0.f;
        #pragma unroll 8
        for (int j = 0; j < H; j++){
            float c = fmaf(W1[2*j], W3[tid], W1[2*j+1] * W3[H + tid]);
            s += W2[tid*H + j] * c;
        }
        sTBL[tid] = make_float4(b2[tid], s, W3[tid], W3[H + tid]);
    }
    __syncthreads();

    const float b30 = sB3[0], b31 = sB3[1];

    // ldmatrix lane address components
    const int aRow  = (lane & 7) + ((lane >> 3) & 1) * 8;     // A x4: rows within 16
    const int aColB = (lane >> 4) * 16;
    const int bRow4 = (lane & 7) + ((lane >> 4) & 1) * 8;     // B x4: n within ng-pair
    const int bCol4 = ((lane >> 3) & 1) * 16;

    const uint32_t aAH = smb + OFF_AH + (uint32_t)((w*32 + aRow)*RS + aColB);
    const uint32_t aNH = smb + OFF_NH + (uint32_t)((w*32 + aRow)*RS + aColB);
    const uint32_t bBase = (uint32_t)(bRow4*RS + bCol4);

    // ---- hoist ALL B fragments into registers (tile-invariant): 128 regs ----
    uint32_t BV[2][4][4][2];   // [half][kc][ng][2]  W2 fragments
    uint32_t BT[2][4][4][2];   //                    M fragments
    #pragma unroll
    for (int half = 0; half < 2; half++)
        #pragma unroll
        for (int kc = 0; kc < 4; kc++)
            #pragma unroll
            for (int ngp = 0; ngp < 2; ngp++){
                uint32_t roff = bBase + (uint32_t)((half*32 + ngp*16)*RS + kc*32);
                uint32_t r[4];
                ldm_x4(r, smb + OFF_W2H + roff);
                BV[half][kc][2*ngp][0] = r[0]; BV[half][kc][2*ngp][1] = r[1];
                BV[half][kc][2*ngp+1][0] = r[2]; BV[half][kc][2*ngp+1][1] = r[3];
                ldm_x4(r, smb + OFF_MH + roff);
                BT[half][kc][2*ngp][0] = r[0]; BT[half][kc][2*ngp][1] = r[1];
                BT[half][kc][2*ngp+1][0] = r[2]; BT[half][kc][2*ngp+1][1] = r[3];
            }

    for (int tile = blockIdx.x; tile < ntiles; tile += gridDim.x){
        const int base = tile * TILE;
        const int s = base + tid;
        const bool ok = (s < B);
        float z0 = 0.f, z1 = 0.f;
        if (ok){ z0 = zlp[3*s]; z1 = zlp[3*s + 1]; }

        // ---- fill this thread's A rows: h and min(h,0) as fp16, 16B chunks ----
        {
            const uint32_t rbase = (uint32_t)tid * RS;
            #pragma unroll
            for (int jb = 0; jb < 8; jb++){
                uint4 vh, un;
                uint32_t* ph = (uint32_t*)&vh;
                uint32_t* pn = (uint32_t*)&un;
                #pragma unroll
                for (int q = 0; q < 4; q++){
                    int j = jb*8 + 2*q;
                    float a0 = fmaf(sW1a[j],   z0, fmaf(sW1b[j],   z1, sB1[j]));
                    float a1 = fmaf(sW1a[j+1], z0, fmaf(sW1b[j+1], z1, sB1[j+1]));
                    float h0 = ok ? elu(a0) : 0.f;
                    float h1 = ok ? elu(a1) : 0.f;
                    ph[q] = packh2(h0, h1);
                    pn[q] = packh2(fminf(h0, 0.f), fminf(h1, 0.f));
                }
                uint32_t o = rbase + jb*16;
                *(uint4*)(sm + OFF_AH + o) = vh;
                *(uint4*)(sm + OFF_NH + o) = un;
            }
        }
        __syncwarp();

        // ---- warp-local GEMM: 32 samples (2 m-tiles), N=64 in 2 halves ----
        float o0[2][2] = {{0,0},{0,0}}, o1[2][2] = {{0,0},{0,0}}, trr[2][2] = {{0,0},{0,0}};

        #pragma unroll
        for (int half = 0; half < 2; half++){
            float dv[2][4][4], dt[2][4][4];
            #pragma unroll
            for (int mt = 0; mt < 2; mt++)
                #pragma unroll
                for (int ng = 0; ng < 4; ng++)
                    #pragma unroll
                    for (int e = 0; e < 4; e++){ dv[mt][ng][e] = 0.f; dt[mt][ng][e] = 0.f; }

            #pragma unroll
            for (int kc = 0; kc < 4; kc++){
                #pragma unroll
                for (int mt = 0; mt < 2; mt++){
                    uint32_t ah[4], nh[4];
                    uint32_t ao = (uint32_t)(mt*16*RS + kc*32);
                    ldm_x4(ah, aAH + ao);
                    ldm_x4(nh, aNH + ao);
                    #pragma unroll
                    for (int ng = 0; ng < 4; ng++){
                        mma_f16(dv[mt][ng], ah, BV[half][kc][ng]);
                        mma_f16(dt[mt][ng], nh, BT[half][kc][ng]);
                    }
                }
            }

            // ---- epilogue for this half ----
            #pragma unroll
            for (int ng = 0; ng < 4; ng++){
                int n0 = half*32 + ng*8 + 2*(lane & 3);
                float4 t0 = sTBL[n0], t1 = sTBL[n0 + 1];
                #pragma unroll
                for (int mt = 0; mt < 2; mt++){
                    #pragma unroll
                    for (int rr = 0; rr < 2; rr++){
                        float v0 = dv[mt][ng][2*rr],     tv0 = dt[mt][ng][2*rr];
                        float v1 = dv[mt][ng][2*rr + 1], tv1 = dt[mt][ng][2*rr + 1];
                        float h2 = elu(v0 + t0.x);
                        o0[mt][rr]  = fmaf(t0.z, h2, o0[mt][rr]);
                        o1[mt][rr]  = fmaf(t0.w, h2, o1[mt][rr]);
                        trr[mt][rr] = fmaf(1.f + fminf(h2, 0.f), tv0 + t0.y, trr[mt][rr]);
                        float h3 = elu(v1 + t1.x);
                        o0[mt][rr]  = fmaf(t1.z, h3, o0[mt][rr]);
                        o1[mt][rr]  = fmaf(t1.w, h3, o1[mt][rr]);
                        trr[mt][rr] = fmaf(1.f + fminf(h3, 0.f), tv1 + t1.y, trr[mt][rr]);
                    }
                }
            }
        }

        // ---- reduce across the 4 lanes of each row group, store ----
        #pragma unroll
        for (int mt = 0; mt < 2; mt++)
            #pragma unroll
            for (int rr = 0; rr < 2; rr++){
                o0[mt][rr]  += __shfl_xor_sync(0xffffffffu, o0[mt][rr], 1);
                o0[mt][rr]  += __shfl_xor_sync(0xffffffffu, o0[mt][rr], 2);
                o1[mt][rr]  += __shfl_xor_sync(0xffffffffu, o1[mt][rr], 1);
                o1[mt][rr]  += __shfl_xor_sync(0xffffffffu, o1[mt][rr], 2);
                trr[mt][rr] += __shfl_xor_sync(0xffffffffu, trr[mt][rr], 1);
                trr[mt][rr] += __shfl_xor_sync(0xffffffffu, trr[mt][rr], 2);
            }
        if ((lane & 3) == 0){
            int g = lane >> 2;
            #pragma unroll
            for (int mt = 0; mt < 2; mt++)
                #pragma unroll
                for (int rr = 0; rr < 2; rr++){
                    int s2 = base + w*32 + mt*16 + g + rr*8;
                    if (s2 < B){
                        out[3*s2]     = o0[mt][rr] + b30;
                        out[3*s2 + 1] = o1[mt][rr] + b31;
                        out[3*s2 + 2] = -trr[mt][rr];
                    }
                }
        }
        __syncwarp();
    }
}

extern "C" void kernel_launch(void* const* d_in, const int* in_sizes, int n_in,
                              void* d_out, int out_size)
{
    // metadata order: t, z_and_logp, W1, b1, W2, b2, W3, b3
    const float* zlp = (const float*)d_in[1];
    const float* W1  = (const float*)d_in[2];
    const float* b1  = (const float*)d_in[3];
    const float* W2  = (const float*)d_in[4];
    const float* b2  = (const float*)d_in[5];
    const float* W3  = (const float*)d_in[6];
    const float* b3  = (const float*)d_in[7];
    float* out = (float*)d_out;
    int B = in_sizes[1] / 3;
    int ntiles = (B + TILE - 1) / TILE;

    cudaFuncSetAttribute(odefunc_mma, cudaFuncAttributeMaxDynamicSharedMemorySize, SMEM_TOTAL);
    int grid = 148;
    if (grid > ntiles) grid = ntiles;
    odefunc_mma<<<grid, NT, SMEM_TOTAL>>>(zlp, W1, b1, W2, b2, W3, b3, out, B, ntiles);
}

// round 8
// speedup vs baseline: 12.4966x; 1.0241x over previous
#include <cuda_runtime.h>
#include <cuda_fp16.h>
#include <cstdint>

#define H 64
#define TILE 256
#define NT 256
#define RS 144                  // smem row stride (bytes): 9*16 -> conflict-free ldmatrix

// ---- smem layout (bytes) ----
#define OFF_AH   0               // h (fp16)        : 256 x 144 = 36864
#define OFF_W2H  36864           // W2 (fp16)       : 64 x 144
#define OFF_MH   46080           // M  (fp16)       : 64 x 144
#define OFF_TBL  55296           // float4[64]: (b2, rsM, W3_0, W3_1)
#define OFF_W1A  56320           // float[64]
#define OFF_W1B  56576
#define OFF_B1   56832
#define OFF_B3   57088           // float[2]
#define SMEM_TOTAL 57344

__device__ __forceinline__ uint32_t smem_u32(const void* p){
    uint32_t a;
    asm("{ .reg .u64 t; cvta.to.shared.u64 t, %1; cvt.u32.u64 %0, t; }" : "=r"(a) : "l"(p));
    return a;
}
__device__ __forceinline__ void ldm_x4(uint32_t* r, uint32_t addr){
    asm volatile("ldmatrix.sync.aligned.m8n8.x4.shared.b16 {%0,%1,%2,%3}, [%4];"
        : "=r"(r[0]),"=r"(r[1]),"=r"(r[2]),"=r"(r[3]) : "r"(addr));
}
__device__ __forceinline__ void mma_f16(float* d, const uint32_t* a, const uint32_t* b){
    asm volatile("mma.sync.aligned.m16n8k16.row.col.f32.f16.f16.f32 "
        "{%0,%1,%2,%3}, {%4,%5,%6,%7}, {%8,%9}, {%0,%1,%2,%3};"
        : "+f"(d[0]),"+f"(d[1]),"+f"(d[2]),"+f"(d[3])
        : "r"(a[0]),"r"(a[1]),"r"(a[2]),"r"(a[3]), "r"(b[0]),"r"(b[1]));
}
__device__ __forceinline__ float elu(float x){ return x > 0.f ? x : (__expf(x) - 1.f); }

__device__ __forceinline__ uint32_t packh2(float a, float b){
    __half2 v = __floats2half2_rn(a, b);
    return *reinterpret_cast<uint32_t*>(&v);
}
// per-half min with 0: nh = min(ah, 0) elementwise on packed fp16
__device__ __forceinline__ uint32_t hmin0(uint32_t v){
    __half2 a = *reinterpret_cast<__half2*>(&v);
    __half2 z = __floats2half2_rn(0.f, 0.f);
    __half2 m = __hmin2(a, z);
    return *reinterpret_cast<uint32_t*>(&m);
}

__global__ __launch_bounds__(NT, 1)
void odefunc_mma(const float* __restrict__ zlp,
                 const float* __restrict__ W1, const float* __restrict__ b1,
                 const float* __restrict__ W2, const float* __restrict__ b2,
                 const float* __restrict__ W3, const float* __restrict__ b3,
                 float* __restrict__ out, int B, int ntiles)
{
    extern __shared__ char sm[];
    const uint32_t smb = smem_u32(sm);
    const int tid = threadIdx.x, w = tid >> 5, lane = tid & 31;

    float*  sW1a = (float*)(sm + OFF_W1A);
    float*  sW1b = (float*)(sm + OFF_W1B);
    float*  sB1  = (float*)(sm + OFF_B1);
    float*  sB3  = (float*)(sm + OFF_B3);
    float4* sTBL = (float4*)(sm + OFF_TBL);

    // ---------- per-CTA weight prep ----------
    for (int j = tid; j < H; j += NT){
        sW1a[j] = W1[2*j]; sW1b[j] = W1[2*j+1]; sB1[j] = b1[j];
    }
    if (tid < 2) sB3[tid] = b3[tid];

    for (int idx = tid; idx < H*H; idx += NT){
        int n = idx >> 6, j = idx & 63;            // n = output neuron, j = input
        float w2 = W2[idx];
        float c  = fmaf(W1[2*j], W3[n], W1[2*j+1] * W3[H + n]);   // C[j][n]
        uint32_t off = (uint32_t)(n*RS + 2*j);
        *(__half*)(sm + OFF_W2H + off) = __float2half_rn(w2);
        *(__half*)(sm + OFF_MH  + off) = __float2half_rn(w2 * c);
    }
    if (tid < H){
        float s = 0.f;
        #pragma unroll 8
        for (int j = 0; j < H; j++){
            float c = fmaf(W1[2*j], W3[tid], W1[2*j+1] * W3[H + tid]);
            s += W2[tid*H + j] * c;
        }
        sTBL[tid] = make_float4(b2[tid], s, W3[tid], W3[H + tid]);
    }
    __syncthreads();

    const float b30 = sB3[0], b31 = sB3[1];

    // ldmatrix lane address components
    const int aRow  = (lane & 7) + ((lane >> 3) & 1) * 8;     // A x4: rows within 16
    const int aColB = (lane >> 4) * 16;
    const int bRow4 = (lane & 7) + ((lane >> 4) & 1) * 8;     // B x4: n within ng-pair
    const int bCol4 = ((lane >> 3) & 1) * 16;

    const uint32_t aAH = smb + OFF_AH + (uint32_t)((w*32 + aRow)*RS + aColB);
    const uint32_t bBase = (uint32_t)(bRow4*RS + bCol4);

    // ---- hoist ALL B fragments into registers (tile-invariant): 128 regs ----
    uint32_t BV[2][4][4][2];   // [half][kc][ng][2]  W2 fragments
    uint32_t BT[2][4][4][2];   //                    M fragments
    #pragma unroll
    for (int half = 0; half < 2; half++)
        #pragma unroll
        for (int kc = 0; kc < 4; kc++)
            #pragma unroll
            for (int ngp = 0; ngp < 2; ngp++){
                uint32_t roff = bBase + (uint32_t)((half*32 + ngp*16)*RS + kc*32);
                uint32_t r[4];
                ldm_x4(r, smb + OFF_W2H + roff);
                BV[half][kc][2*ngp][0] = r[0]; BV[half][kc][2*ngp][1] = r[1];
                BV[half][kc][2*ngp+1][0] = r[2]; BV[half][kc][2*ngp+1][1] = r[3];
                ldm_x4(r, smb + OFF_MH + roff);
                BT[half][kc][2*ngp][0] = r[0]; BT[half][kc][2*ngp][1] = r[1];
                BT[half][kc][2*ngp+1][0] = r[2]; BT[half][kc][2*ngp+1][1] = r[3];
            }

    for (int tile = blockIdx.x; tile < ntiles; tile += gridDim.x){
        const int base = tile * TILE;
        const int s = base + tid;
        const bool ok = (s < B);
        float z0 = 0.f, z1 = 0.f;
        if (ok){ z0 = zlp[3*s]; z1 = zlp[3*s + 1]; }

        // ---- fill this thread's A row: h as fp16, 16B chunks ----
        {
            const uint32_t rbase = (uint32_t)tid * RS;
            #pragma unroll
            for (int jb = 0; jb < 8; jb++){
                uint4 vh;
                uint32_t* ph = (uint32_t*)&vh;
                #pragma unroll
                for (int q = 0; q < 4; q++){
                    int j = jb*8 + 2*q;
                    float a0 = fmaf(sW1a[j],   z0, fmaf(sW1b[j],   z1, sB1[j]));
                    float a1 = fmaf(sW1a[j+1], z0, fmaf(sW1b[j+1], z1, sB1[j+1]));
                    float h0 = ok ? elu(a0) : 0.f;
                    float h1 = ok ? elu(a1) : 0.f;
                    ph[q] = packh2(h0, h1);
                }
                *(uint4*)(sm + OFF_AH + rbase + jb*16) = vh;
            }
        }
        __syncwarp();

        // ---- warp-local GEMM: mt outer to bound live registers ----
        float o0[2][2], o1[2][2], trr[2][2];

        #pragma unroll
        for (int mt = 0; mt < 2; mt++){
            // load A fragments for this m-tile, all kc: 4 ldsm; derive N-plane via hmin
            uint32_t ah[4][4], nh[4][4];
            #pragma unroll
            for (int kc = 0; kc < 4; kc++){
                ldm_x4(ah[kc], aAH + (uint32_t)(mt*16*RS + kc*32));
                #pragma unroll
                for (int e = 0; e < 4; e++) nh[kc][e] = hmin0(ah[kc][e]);
            }

            float oo0[2] = {0.f, 0.f}, oo1[2] = {0.f, 0.f}, tt[2] = {0.f, 0.f};

            #pragma unroll
            for (int half = 0; half < 2; half++){
                float dv[4][4], dt[4][4];
                #pragma unroll
                for (int ng = 0; ng < 4; ng++)
                    #pragma unroll
                    for (int e = 0; e < 4; e++){ dv[ng][e] = 0.f; dt[ng][e] = 0.f; }

                #pragma unroll
                for (int kc = 0; kc < 4; kc++)
                    #pragma unroll
                    for (int ng = 0; ng < 4; ng++){
                        mma_f16(dv[ng], ah[kc], BV[half][kc][ng]);
                        mma_f16(dt[ng], nh[kc], BT[half][kc][ng]);
                    }

                // epilogue for this (mt, half)
                #pragma unroll
                for (int ng = 0; ng < 4; ng++){
                    int n0 = half*32 + ng*8 + 2*(lane & 3);
                    float4 t0 = sTBL[n0], t1 = sTBL[n0 + 1];
                    #pragma unroll
                    for (int rr = 0; rr < 2; rr++){
                        float v0 = dv[ng][2*rr],     tv0 = dt[ng][2*rr];
                        float v1 = dv[ng][2*rr + 1], tv1 = dt[ng][2*rr + 1];
                        float h2 = elu(v0 + t0.x);
                        oo0[rr] = fmaf(t0.z, h2, oo0[rr]);
                        oo1[rr] = fmaf(t0.w, h2, oo1[rr]);
                        tt[rr]  = fmaf(1.f + fminf(h2, 0.f), tv0 + t0.y, tt[rr]);
                        float h3 = elu(v1 + t1.x);
                        oo0[rr] = fmaf(t1.z, h3, oo0[rr]);
                        oo1[rr] = fmaf(t1.w, h3, oo1[rr]);
                        tt[rr]  = fmaf(1.f + fminf(h3, 0.f), tv1 + t1.y, tt[rr]);
                    }
                }
            }
            #pragma unroll
            for (int rr = 0; rr < 2; rr++){
                o0[mt][rr] = oo0[rr]; o1[mt][rr] = oo1[rr]; trr[mt][rr] = tt[rr];
            }
        }

        // ---- reduce across the 4 lanes of each row group, store ----
        #pragma unroll
        for (int mt = 0; mt < 2; mt++)
            #pragma unroll
            for (int rr = 0; rr < 2; rr++){
                o0[mt][rr]  += __shfl_xor_sync(0xffffffffu, o0[mt][rr], 1);
                o0[mt][rr]  += __shfl_xor_sync(0xffffffffu, o0[mt][rr], 2);
                o1[mt][rr]  += __shfl_xor_sync(0xffffffffu, o1[mt][rr], 1);
                o1[mt][rr]  += __shfl_xor_sync(0xffffffffu, o1[mt][rr], 2);
                trr[mt][rr] += __shfl_xor_sync(0xffffffffu, trr[mt][rr], 1);
                trr[mt][rr] += __shfl_xor_sync(0xffffffffu, trr[mt][rr], 2);
            }
        if ((lane & 3) == 0){
            int g = lane >> 2;
            #pragma unroll
            for (int mt = 0; mt < 2; mt++)
                #pragma unroll
                for (int rr = 0; rr < 2; rr++){
                    int s2 = base + w*32 + mt*16 + g + rr*8;
                    if (s2 < B){
                        out[3*s2]     = o0[mt][rr] + b30;
                        out[3*s2 + 1] = o1[mt][rr] + b31;
                        out[3*s2 + 2] = -trr[mt][rr];
                    }
                }
        }
        __syncwarp();
    }
}

extern "C" void kernel_launch(void* const* d_in, const int* in_sizes, int n_in,
                              void* d_out, int out_size)
{
    // metadata order: t, z_and_logp, W1, b1, W2, b2, W3, b3
    const float* zlp = (const float*)d_in[1];
    const float* W1  = (const float*)d_in[2];
    const float* b1  = (const float*)d_in[3];
    const float* W2  = (const float*)d_in[4];
    const float* b2  = (const float*)d_in[5];
    const float* W3  = (const float*)d_in[6];
    const float* b3  = (const float*)d_in[7];
    float* out = (float*)d_out;
    int B = in_sizes[1] / 3;
    int ntiles = (B + TILE - 1) / TILE;

    cudaFuncSetAttribute(odefunc_mma, cudaFuncAttributeMaxDynamicSharedMemorySize, SMEM_TOTAL);
    int grid = 148;
    if (grid > ntiles) grid = ntiles;
    odefunc_mma<<<grid, NT, SMEM_TOTAL>>>(zlp, W1, b1, W2, b2, W3, b3, out, B, ntiles);
}

// round 10
// speedup vs baseline: 16.4072x; 1.3129x over previous
#include <cuda_runtime.h>
#include <cuda_fp16.h>
#include <cstdint>

#define H 64
#define TILE 256
#define NT 256
#define RS 144                  // smem row stride (bytes): 9*16 -> conflict-free ldmatrix

// ---- smem layout (bytes) ----
#define OFF_AH   0               // h (fp16)        : 256 x 144 = 36864
#define OFF_W2H  36864           // W2 (fp16)       : 64 x 144
#define OFF_MH   46080           // M  (fp16)       : 64 x 144
#define OFF_TBL  55296           // float4[64]: (b2, rsM, W3_0, W3_1)
#define OFF_W1A  56320           // float[64]
#define OFF_W1B  56576
#define OFF_B1   56832
#define OFF_B3   57088           // float[2]
#define SMEM_TOTAL 57344

__device__ __forceinline__ uint32_t smem_u32(const void* p){
    uint32_t a;
    asm("{ .reg .u64 t; cvta.to.shared.u64 t, %1; cvt.u32.u64 %0, t; }" : "=r"(a) : "l"(p));
    return a;
}
__device__ __forceinline__ void ldm_x4(uint32_t* r, uint32_t addr){
    asm volatile("ldmatrix.sync.aligned.m8n8.x4.shared.b16 {%0,%1,%2,%3}, [%4];"
        : "=r"(r[0]),"=r"(r[1]),"=r"(r[2]),"=r"(r[3]) : "r"(addr));
}
__device__ __forceinline__ void mma_f16(float* d, const uint32_t* a, const uint32_t* b){
    asm volatile("mma.sync.aligned.m16n8k16.row.col.f32.f16.f16.f32 "
        "{%0,%1,%2,%3}, {%4,%5,%6,%7}, {%8,%9}, {%0,%1,%2,%3};"
        : "+f"(d[0]),"+f"(d[1]),"+f"(d[2]),"+f"(d[3])
        : "r"(a[0]),"r"(a[1]),"r"(a[2]),"r"(a[3]), "r"(b[0]),"r"(b[1]));
}
__device__ __forceinline__ float elu(float x){ return x > 0.f ? x : (__expf(x) - 1.f); }

__device__ __forceinline__ uint32_t packh2(float a, float b){
    __half2 v = __floats2half2_rn(a, b);
    return *reinterpret_cast<uint32_t*>(&v);
}
// elementwise min(x, 0) on packed fp16
__device__ __forceinline__ uint32_t hmin0(uint32_t v){
    __half2 a = *reinterpret_cast<__half2*>(&v);
    __half2 z = __floats2half2_rn(0.f, 0.f);
    __half2 m = __hmin2(a, z);
    return *reinterpret_cast<uint32_t*>(&m);
}

__global__ __launch_bounds__(NT, 2)
void odefunc_mma(const float* __restrict__ zlp,
                 const float* __restrict__ W1, const float* __restrict__ b1,
                 const float* __restrict__ W2, const float* __restrict__ b2,
                 const float* __restrict__ W3, const float* __restrict__ b3,
                 float* __restrict__ out, int B, int ntiles)
{
    extern __shared__ char sm[];
    const uint32_t smb = smem_u32(sm);
    const int tid = threadIdx.x, w = tid >> 5, lane = tid & 31;

    float*  sW1a = (float*)(sm + OFF_W1A);
    float*  sW1b = (float*)(sm + OFF_W1B);
    float*  sB1  = (float*)(sm + OFF_B1);
    float*  sB3  = (float*)(sm + OFF_B3);
    float4* sTBL = (float4*)(sm + OFF_TBL);

    // ---------- per-CTA weight prep ----------
    for (int j = tid; j < H; j += NT){
        sW1a[j] = W1[2*j]; sW1b[j] = W1[2*j+1]; sB1[j] = b1[j];
    }
    if (tid < 2) sB3[tid] = b3[tid];

    for (int idx = tid; idx < H*H; idx += NT){
        int n = idx >> 6, j = idx & 63;            // n = output neuron, j = input
        float w2 = W2[idx];
        float c  = fmaf(W1[2*j], W3[n], W1[2*j+1] * W3[H + n]);   // C[j][n]
        uint32_t off = (uint32_t)(n*RS + 2*j);
        *(__half*)(sm + OFF_W2H + off) = __float2half_rn(w2);
        *(__half*)(sm + OFF_MH  + off) = __float2half_rn(w2 * c);
    }
    if (tid < H){
        float s = 0.f;
        #pragma unroll 8
        for (int j = 0; j < H; j++){
            float c = fmaf(W1[2*j], W3[tid], W1[2*j+1] * W3[H + tid]);
            s += W2[tid*H + j] * c;
        }
        sTBL[tid] = make_float4(b2[tid], s, W3[tid], W3[H + tid]);
    }
    __syncthreads();

    const float b30 = sB3[0], b31 = sB3[1];

    // ldmatrix lane address components
    const int aRow  = (lane & 7) + ((lane >> 3) & 1) * 8;     // A x4: rows within 16
    const int aColB = (lane >> 4) * 16;
    const int bRow4 = (lane & 7) + ((lane >> 4) & 1) * 8;     // B x4: n within ng-pair
    const int bCol4 = ((lane >> 3) & 1) * 16;

    const uint32_t aAH  = smb + OFF_AH + (uint32_t)((w*32 + aRow)*RS + aColB);
    const uint32_t bW2  = smb + OFF_W2H + (uint32_t)(bRow4*RS + bCol4);
    const uint32_t bM   = smb + OFF_MH  + (uint32_t)(bRow4*RS + bCol4);

    for (int tile = blockIdx.x; tile < ntiles; tile += gridDim.x){
        const int base = tile * TILE;
        const int s = base + tid;
        const bool ok = (s < B);
        float z0 = 0.f, z1 = 0.f;
        if (ok){ z0 = zlp[3*s]; z1 = zlp[3*s + 1]; }

        // ---- fill this thread's A row: h as fp16, 16B chunks ----
        {
            const uint32_t rbase = (uint32_t)tid * RS;
            #pragma unroll
            for (int jb = 0; jb < 8; jb++){
                uint4 vh;
                uint32_t* ph = (uint32_t*)&vh;
                #pragma unroll
                for (int q = 0; q < 4; q++){
                    int j = jb*8 + 2*q;
                    float a0 = fmaf(sW1a[j],   z0, fmaf(sW1b[j],   z1, sB1[j]));
                    float a1 = fmaf(sW1a[j+1], z0, fmaf(sW1b[j+1], z1, sB1[j+1]));
                    float h0 = ok ? elu(a0) : 0.f;
                    float h1 = ok ? elu(a1) : 0.f;
                    ph[q] = packh2(h0, h1);
                }
                *(uint4*)(sm + OFF_AH + rbase + jb*16) = vh;
            }
        }
        __syncwarp();

        // ---- warp-local GEMM: mt outer; B fragments loaded JIT from smem ----
        #pragma unroll
        for (int mt = 0; mt < 2; mt++){
            // A fragments for this m-tile, all kc (16 regs)
            uint32_t ah[4][4];
            #pragma unroll
            for (int kc = 0; kc < 4; kc++)
                ldm_x4(ah[kc], aAH + (uint32_t)(mt*16*RS + kc*32));

            float o0[2] = {0.f, 0.f}, o1[2] = {0.f, 0.f}, tr[2] = {0.f, 0.f};

            #pragma unroll
            for (int half = 0; half < 2; half++){
                float dv[4][4], dt[4][4];
                #pragma unroll
                for (int ng = 0; ng < 4; ng++)
                    #pragma unroll
                    for (int e = 0; e < 4; e++){ dv[ng][e] = 0.f; dt[ng][e] = 0.f; }

                #pragma unroll
                for (int kc = 0; kc < 4; kc++){
                    uint32_t roff0 = (uint32_t)((half*32     )*RS + kc*32);
                    uint32_t roff1 = (uint32_t)((half*32 + 16)*RS + kc*32);
                    uint32_t bv[8], bm[8];
                    ldm_x4(bv,     bW2 + roff0);
                    ldm_x4(bv + 4, bW2 + roff1);
                    ldm_x4(bm,     bM  + roff0);
                    ldm_x4(bm + 4, bM  + roff1);
                    uint32_t nh[4];
                    #pragma unroll
                    for (int e = 0; e < 4; e++) nh[e] = hmin0(ah[kc][e]);
                    #pragma unroll
                    for (int ng = 0; ng < 4; ng++){
                        mma_f16(dv[ng], ah[kc], bv + 2*ng);
                        mma_f16(dt[ng], nh,     bm + 2*ng);
                    }
                }

                // epilogue for this (mt, half)
                #pragma unroll
                for (int ng = 0; ng < 4; ng++){
                    int n0 = half*32 + ng*8 + 2*(lane & 3);
                    float4 t0 = sTBL[n0], t1 = sTBL[n0 + 1];
                    #pragma unroll
                    for (int rr = 0; rr < 2; rr++){
                        float v0 = dv[ng][2*rr],     tv0 = dt[ng][2*rr];
                        float v1 = dv[ng][2*rr + 1], tv1 = dt[ng][2*rr + 1];
                        float h2 = elu(v0 + t0.x);
                        o0[rr] = fmaf(t0.z, h2, o0[rr]);
                        o1[rr] = fmaf(t0.w, h2, o1[rr]);
                        tr[rr] = fmaf(1.f + fminf(h2, 0.f), tv0 + t0.y, tr[rr]);
                        float h3 = elu(v1 + t1.x);
                        o0[rr] = fmaf(t1.z, h3, o0[rr]);
                        o1[rr] = fmaf(t1.w, h3, o1[rr]);
                        tr[rr] = fmaf(1.f + fminf(h3, 0.f), tv1 + t1.y, tr[rr]);
                    }
                }
            }

            // ---- reduce across the 4 lanes of each row group, store (per mt) ----
            #pragma unroll
            for (int rr = 0; rr < 2; rr++){
                o0[rr] += __shfl_xor_sync(0xffffffffu, o0[rr], 1);
                o0[rr] += __shfl_xor_sync(0xffffffffu, o0[rr], 2);
                o1[rr] += __shfl_xor_sync(0xffffffffu, o1[rr], 1);
                o1[rr] += __shfl_xor_sync(0xffffffffu, o1[rr], 2);
                tr[rr] += __shfl_xor_sync(0xffffffffu, tr[rr], 1);
                tr[rr] += __shfl_xor_sync(0xffffffffu, tr[rr], 2);
            }
            if ((lane & 3) == 0){
                int g = lane >> 2;
                #pragma unroll
                for (int rr = 0; rr < 2; rr++){
                    int s2 = base + w*32 + mt*16 + g + rr*8;
                    if (s2 < B){
                        out[3*s2]     = o0[rr] + b30;
                        out[3*s2 + 1] = o1[rr] + b31;
                        out[3*s2 + 2] = -tr[rr];
                    }
                }
            }
        }
        __syncwarp();
    }
}

extern "C" void kernel_launch(void* const* d_in, const int* in_sizes, int n_in,
                              void* d_out, int out_size)
{
    // metadata order: t, z_and_logp, W1, b1, W2, b2, W3, b3
    const float* zlp = (const float*)d_in[1];
    const float* W1  = (const float*)d_in[2];
    const float* b1  = (const float*)d_in[3];
    const float* W2  = (const float*)d_in[4];
    const float* b2  = (const float*)d_in[5];
    const float* W3  = (const float*)d_in[6];
    const float* b3  = (const float*)d_in[7];
    float* out = (float*)d_out;
    int B = in_sizes[1] / 3;
    int ntiles = (B + TILE - 1) / TILE;

    cudaFuncSetAttribute(odefunc_mma, cudaFuncAttributeMaxDynamicSharedMemorySize, SMEM_TOTAL);
    int grid = 296;               // 2 CTAs x 148 SMs, persistent
    if (grid > ntiles) grid = ntiles;
    odefunc_mma<<<grid, NT, SMEM_TOTAL>>>(zlp, W1, b1, W2, b2, W3, b3, out, B, ntiles);
}